// round 14
// baseline (speedup 1.0000x reference)
#include <cuda_runtime.h>
#include <cstdint>

#define NQ    32
#define KCB   1024
#define CDIM  8
#define DDIM  1024
#define BDIMS 8
#define TDIM  4096
#define TILE  32
#define NTH   512
#define NCOLS (BDIMS*TDIM)          /* 32768 */
#define BDT   (BDIMS*DDIM*TDIM)     /* 33554432 */
#define NQBT  (NQ*NCOLS)            /* 1048576 */

/* shared memory offsets (floats) */
#define SM_R    0                   /* 1024 x 32 residual, swizzled float4  */
#define SM_W    32768               /* 8 x 1024 : iw (P1) then owT (P3)     */
#define SM_CBT  40960               /* cbT: 8 x 1024                        */
#define SM_C2   49152               /* 1024                                 */
#define SM_ZE   50176               /* 32 x 9                               */
#define SM_PART 50464               /* 16 w x 32 ull = 1024 floats          */
#define SM_ZQP  51488               /* 16 pairs x 8 c x ull = 256 floats    */
#define SM_M    51744               /* 32                                   */
#define SM_BD   51776               /* 512                                  */
#define SM_BK   52288               /* 512                                  */
#define SM_TOT  52800
#define SM_BYTES (SM_TOT*4)

typedef unsigned long long ull;

__device__ float g_owT[NQ * CDIM * DDIM];   /* [q][c][d] */
__device__ float g_cbT[NQ * CDIM * KCB];    /* [q][c][k] */
__device__ float g_c2 [NQ * KCB];           /* |cb|^2    */
__device__ float g_Vc [256];                /* [q*8+c] = iw^q[c] . obpre^q */
__device__ float g_obpre[NQ * DDIM];        /* prefix sum of ob (p < q)    */
__device__ float g_obsum[DDIM];             /* total sum of ob             */

__device__ __forceinline__ ull f2x(float lo, float hi) {
    ull r;
    asm("mov.b64 %0, {%1, %2};" : "=l"(r)
        : "r"(__float_as_uint(lo)), "r"(__float_as_uint(hi)));
    return r;
}
__device__ __forceinline__ void upk(ull v, float& lo, float& hi) {
    unsigned a, b;
    asm("mov.b64 {%0, %1}, %2;" : "=r"(a), "=r"(b) : "l"(v));
    lo = __uint_as_float(a); hi = __uint_as_float(b);
}
#define FMA2(D,A,B,C) asm("fma.rn.f32x2 %0, %1, %2, %3;" : "=l"(D) : "l"(A), "l"(B), "l"(C))
#define ADD2(D,A,B)   asm("add.rn.f32x2 %0, %1, %2;"     : "=l"(D) : "l"(A), "l"(B))

__device__ __forceinline__ unsigned s2u(const void* p) {
    unsigned a;
    asm("{ .reg .u64 t; cvta.to.shared.u64 t, %1; cvt.u32.u64 %0, t; }"
        : "=r"(a) : "l"(p));
    return a;
}
__device__ __forceinline__ void cpa16(unsigned saddr, const void* g) {
    asm volatile("cp.async.cg.shared.global [%0], [%1], 16;" :: "r"(saddr), "l"(g));
}
#define CPA_COMMIT() asm volatile("cp.async.commit_group;")
#define CPA_WAIT0()  asm volatile("cp.async.wait_group 0;")
#define CPA_WAIT1()  asm volatile("cp.async.wait_group 1;")

/* ---------- prep A: ob prefix sums ---------- */
__global__ void prep0_kernel(const float* __restrict__ ob)
{
    int d = blockIdx.x * blockDim.x + threadIdx.x;
    if (d < DDIM) {
        float run = 0.f;
        for (int p = 0; p < NQ; p++) {
            g_obpre[p * DDIM + d] = run;
            run += ob[p * DDIM + d];
        }
        g_obsum[d] = run;
    }
}

/* ---------- prep B: transposes + |cb|^2 ---------- */
__global__ void prep_kernel(const float* __restrict__ ow,
                            const float* __restrict__ cb)
{
    int idx = blockIdx.x * blockDim.x + threadIdx.x;
    int stride = gridDim.x * blockDim.x;
    for (int i = idx; i < NQ * CDIM * DDIM; i += stride) {
        int q = i >> 13, r = i & 8191, c = r >> 10, d = r & 1023;
        g_owT[i] = ow[(q << 13) + (d << 3) + c];
    }
    for (int i = idx; i < NQ * CDIM * KCB; i += stride) {
        int q = i >> 13, r = i & 8191, c = r >> 10, k = r & 1023;
        g_cbT[i] = cb[(q << 13) + (k << 3) + c];
    }
    for (int k = idx; k < NQ * KCB; k += stride) {
        const float4* row = (const float4*)(cb + (size_t)k * 8);
        float4 a = row[0], b4 = row[1];
        float p = fmaf(a.x, a.x, fmaf(a.y, a.y, fmaf(a.z, a.z, a.w * a.w)));
        float o = fmaf(b4.x, b4.x, fmaf(b4.y, b4.y, fmaf(b4.z, b4.z, b4.w * b4.w)));
        g_c2[k] = p + o;
    }
}

/* ---------- prep C: Vc[q][c] = iw^q[c] . obpre[q] ---------- */
__global__ void prepVc_kernel(const float* __restrict__ iw)
{
    int q = blockIdx.x;
    __shared__ float ps[256];
    int tid = threadIdx.x;
    int c = tid >> 5, slice = tid & 31;
    const float* iwr = iw + (q << 13) + (c << 10) + slice * 32;
    const float* obr = g_obpre + (q << 10) + slice * 32;
    float s = 0.f;
    for (int d = 0; d < 32; d++) s = fmaf(iwr[d], obr[d], s);
    ps[tid] = s;
    __syncthreads();
    if (tid < 8) {
        float t = 0.f;
        #pragma unroll
        for (int j = 0; j < 32; j++) t += ps[tid * 32 + j];
        g_Vc[q * 8 + tid] = t;
    }
}

__global__ __launch_bounds__(NTH, 1)
void rvq_kernel(const float* __restrict__ z,
                const float* __restrict__ iw,
                const float* __restrict__ ibias,
                const float* __restrict__ cb,
                const int*   __restrict__ inlen,
                float* __restrict__ out,
                int wout, int widx, int wlen)
{
    extern __shared__ float sm[];
    float* r_s   = sm + SM_R;
    float* w_s   = sm + SM_W;
    float* cbt_s = sm + SM_CBT;
    float* c2_s  = sm + SM_C2;
    float* ze_s  = sm + SM_ZE;
    ull*   partu = (ull*)(sm + SM_PART);
    float* partf = sm + SM_PART;
    ull*   zqp_u = (ull*)(sm + SM_ZQP);
    float* zqp_f = sm + SM_ZQP;
    float* m_s   = sm + SM_M;
    float* bd_s  = sm + SM_BD;
    int*   bk_s  = (int*)(sm + SM_BK);
    float4* R4   = (float4*)r_s;

    const unsigned sw_u   = s2u(w_s);
    const unsigned scbt_u = s2u(cbt_s);
    const unsigned sc2_u  = s2u(c2_s);

    const int tid  = threadIdx.x;
    const int lane = tid & 31;
    const int w    = tid >> 5;          /* 0..15 */
    /* P1 & P3 decomposition: 4 t-groups x 4 d-slices */
    const int tg   = w >> 2;            /* 0..3 : 8-t group   */
    const int dg   = w & 3;             /* 0..3 : 256-d slice */
    const int tqa  = tg << 1, tqb = tqa + 1;

    const int col0 = blockIdx.x * TILE;
    const int b    = col0 >> 12;
    const int t0   = col0 & (TDIM - 1);
    const int len  = inlen[b];

    const float* zb = z + (size_t)b * DDIM * TDIM + t0;

    /* staging: 32KB arrays = 4 x 16B per thread; 4KB = 256 x 16B */
    #define STAGE32(dstu, src) do {                                        \
        const float4* _g = (const float4*)(src);                           \
        cpa16((dstu) + tid * 16,                (const void*)(_g + tid));  \
        cpa16((dstu) + (tid + 512) * 16,  (const void*)(_g + tid + 512));  \
        cpa16((dstu) + (tid + 1024) * 16, (const void*)(_g + tid + 1024)); \
        cpa16((dstu) + (tid + 1536) * 16, (const void*)(_g + tid + 1536)); \
    } while (0)
    #define STAGE4(dstu, src) do {                                         \
        if (tid < 256) {                                                   \
            const float4* _g = (const float4*)(src);                       \
            cpa16((dstu) + tid * 16, (const void*)(_g + tid));             \
        }                                                                  \
    } while (0)

    if (tid < TILE) m_s[tid] = ((t0 + tid) < len) ? 1.0f : 0.0f;

    /* kick q=0 staging while we fill R */
    STAGE32(sw_u,   iw);
    STAGE32(scbt_u, g_cbT);
    STAGE4(sc2_u,   g_c2);
    CPA_COMMIT();

    /* ---- init residual(no-ob form) = z * mask ---- */
    #pragma unroll
    for (int it = 0; it < 16; it++) {
        int i = tid + it * NTH;
        int d = i >> 3, tq = i & 7;
        float4 v = *(const float4*)(zb + (size_t)d * TDIM + (tq << 2));
        int tb = t0 + (tq << 2);
        v.x = (tb + 0 < len) ? v.x : 0.0f;
        v.y = (tb + 1 < len) ? v.y : 0.0f;
        v.z = (tb + 2 < len) ? v.z : 0.0f;
        v.w = (tb + 3 < len) ? v.w : 0.0f;
        R4[d * 8 + (tq ^ (d & 7))] = v;
    }

    for (int q = 0; q < NQ; q++) {
        CPA_WAIT0();
        __syncthreads();

        /* ====== phase 1 (packed, 4tg x 4dg): 8 t x 256 d per warp ====== */
        {
            ull v[32];
            #pragma unroll
            for (int i = 0; i < 32; i++) v[i] = 0ull;

            #pragma unroll 2
            for (int i = 0; i < 8; i++) {
                int d = dg * 256 + (i << 5) + lane;
                ulonglong2 rA = *(const ulonglong2*)&R4[d * 8 + (tqa ^ (d & 7))];
                ulonglong2 rB = *(const ulonglong2*)&R4[d * 8 + (tqb ^ (d & 7))];
                #pragma unroll
                for (int c = 0; c < 8; c++) {
                    float wv = w_s[c * 1024 + d];
                    ull wd = f2x(wv, wv);
                    FMA2(v[c * 4 + 0], wd, rA.x, v[c * 4 + 0]);
                    FMA2(v[c * 4 + 1], wd, rA.y, v[c * 4 + 1]);
                    FMA2(v[c * 4 + 2], wd, rB.x, v[c * 4 + 2]);
                    FMA2(v[c * 4 + 3], wd, rB.y, v[c * 4 + 3]);
                }
            }
            /* split-exchange: 32 ull over 32 lanes -> lane l holds item l */
            int n = 32;
            #pragma unroll
            for (int off = 16; off >= 1; off >>= 1) {
                n >>= 1;
                bool hi = (lane & off) != 0;
                #pragma unroll
                for (int i = 0; i < 16; i++) {
                    if (i < n) {
                        ull send = hi ? v[i] : v[i + n];
                        ull recv = __shfl_xor_sync(0xffffffffu, send, off);
                        ull keep = hi ? v[i + n] : v[i];
                        ADD2(v[i], keep, recv);
                    }
                }
            }
            partu[w * 32 + lane] = v[0];
        }
        __syncthreads();

        /* ---- issue ow[q] async (w_s free), combine partials -> ze ----
           ze += ib - m*Vc   (ob hoisted out of the residual)            */
        STAGE32(sw_u, g_owT + ((size_t)q << 13));
        CPA_COMMIT();
        if (tid < 256) {
            int t = tid >> 3, c = tid & 7;
            int tgg = t >> 3, rem = t & 7, j = rem >> 1, h = rem & 1;
            int item = c * 4 + j;
            float s = partf[((tgg * 4 + 0) * 32 + item) * 2 + h]
                    + partf[((tgg * 4 + 1) * 32 + item) * 2 + h]
                    + partf[((tgg * 4 + 2) * 32 + item) * 2 + h]
                    + partf[((tgg * 4 + 3) * 32 + item) * 2 + h]
                    + ibias[q * CDIM + c]
                    - m_s[t] * g_Vc[q * 8 + c];
            ze_s[t * 9 + c] = s;
        }
        __syncthreads();

        /* ====== phase 2 (packed k-quads): lane = t, warp = 64 k's ====== */
        {
            int t = lane;
            ull ed[8];
            #pragma unroll
            for (int c = 0; c < 8; c++) {
                float e = ze_s[t * 9 + c];
                ed[c] = f2x(e, e);
            }
            const ull n2 = f2x(-2.0f, -2.0f);
            float best = 3.402823466e38f;
            int bk = 0;
            const int kb = w << 6;
            #pragma unroll 4
            for (int i = 0; i < 16; i++) {
                int k = kb + (i << 2);
                ull sA = 0ull, sB = 0ull;
                #pragma unroll
                for (int c = 0; c < 8; c++) {
                    ulonglong2 cv = *(const ulonglong2*)(cbt_s + c * 1024 + k);
                    FMA2(sA, cv.x, ed[c], sA);
                    FMA2(sB, cv.y, ed[c], sB);
                }
                ulonglong2 c2v = *(const ulonglong2*)(c2_s + k);
                ull bA, bB;
                FMA2(bA, sA, n2, c2v.x);   /* dist = c2 - 2s (e2 rank-invariant) */
                FMA2(bB, sB, n2, c2v.y);
                float da, db, dc, dd;
                upk(bA, da, db); upk(bB, dc, dd);
                if (da < best) { best = da; bk = k;     }
                if (db < best) { best = db; bk = k + 1; }
                if (dc < best) { best = dc; bk = k + 2; }
                if (dd < best) { best = dd; bk = k + 3; }
            }
            bd_s[w * 32 + t] = best;
            bk_s[w * 32 + t] = bk;
        }
        __syncthreads();

        /* ---- prefetch cbT/c2[q+1] (region idle), select, wait ow ---- */
        if (q + 1 < NQ) {
            STAGE32(scbt_u, g_cbT + ((size_t)(q + 1) << 13));
            STAGE4(sc2_u,   g_c2 + ((size_t)(q + 1) << 10));
        }
        CPA_COMMIT();
        if (tid < TILE) {
            int t = tid;
            float best = bd_s[t];
            int bk = bk_s[t];
            #pragma unroll
            for (int kc = 1; kc < 16; kc++) {
                float d2 = bd_s[kc * 32 + t];
                if (d2 < best) { best = d2; bk = bk_s[kc * 32 + t]; }
            }
            if (widx) out[BDT + q * NCOLS + col0 + t] = (float)bk;
            float mt = m_s[t];
            const float4* cr = (const float4*)(cb + (((size_t)q << 10) + bk) * 8);
            float4 ca = cr[0], cb4 = cr[1];
            /* pair = t>>1, half = t&1 ; zqp_u[pair*8+c] */
            float* zp = zqp_f + (t >> 1) * 16 + (t & 1);
            zp[0]  = -ca.x * mt;  zp[2]  = -ca.y * mt;
            zp[4]  = -ca.z * mt;  zp[6]  = -ca.w * mt;
            zp[8]  = -cb4.x * mt; zp[10] = -cb4.y * mt;
            zp[12] = -cb4.z * mt; zp[14] = -cb4.w * mt;
        }
        CPA_WAIT1();            /* ow[q] done; cbT[q+1] may stay in flight */
        __syncthreads();

        /* ====== phase 3 (packed, 4tg x 4dg): r -= ow.zq  (no ob) ======
           ra.x = pair 4tg+0, ra.y = 4tg+1, rb.x = 4tg+2, rb.y = 4tg+3   */
        {
            ull zq0[8], zq1[8], zq2[8], zq3[8];
            #pragma unroll
            for (int c = 0; c < 8; c++) {
                zq0[c] = zqp_u[(tg * 4 + 0) * 8 + c];
                zq1[c] = zqp_u[(tg * 4 + 1) * 8 + c];
                zq2[c] = zqp_u[(tg * 4 + 2) * 8 + c];
                zq3[c] = zqp_u[(tg * 4 + 3) * 8 + c];
            }
            #pragma unroll 2
            for (int i = 0; i < 8; i++) {
                int d = dg * 256 + (i << 5) + lane;
                int sA = d * 8 + (tqa ^ (d & 7));
                int sB = d * 8 + (tqb ^ (d & 7));
                ulonglong2 ra = *(const ulonglong2*)&R4[sA];
                ulonglong2 rb = *(const ulonglong2*)&R4[sB];
                #pragma unroll
                for (int c = 0; c < 8; c++) {
                    float wv = w_s[c * 1024 + d];
                    ull wd = f2x(wv, wv);
                    FMA2(ra.x, wd, zq0[c], ra.x);
                    FMA2(ra.y, wd, zq1[c], ra.y);
                    FMA2(rb.x, wd, zq2[c], rb.x);
                    FMA2(rb.y, wd, zq3[c], rb.y);
                }
                *(ulonglong2*)&R4[sA] = ra;
                *(ulonglong2*)&R4[sB] = rb;
            }
        }
        __syncthreads();

        /* ---- issue iw[q+1] (w_s free post-barrier) ---- */
        if (q + 1 < NQ) {
            STAGE32(sw_u, iw + ((size_t)(q + 1) << 13));
        }
        CPA_COMMIT();
    }

    /* ---- epilogue: qout = z*m - r_noob + obsum*m ---- */
    if (wout) {
        #pragma unroll
        for (int it = 0; it < 16; it++) {
            int i = tid + it * NTH;
            int d = i >> 3, tq = i & 7;
            float4 zv = *(const float4*)(zb + (size_t)d * TDIM + (tq << 2));
            float4 rv = R4[d * 8 + (tq ^ (d & 7))];
            float obv = g_obsum[d];
            int tb = t0 + (tq << 2);
            float4 o;
            o.x = ((tb + 0 < len) ? zv.x + obv : 0.0f) - rv.x;
            o.y = ((tb + 1 < len) ? zv.y + obv : 0.0f) - rv.y;
            o.z = ((tb + 2 < len) ? zv.z + obv : 0.0f) - rv.z;
            o.w = ((tb + 3 < len) ? zv.w + obv : 0.0f) - rv.w;
            *(float4*)(out + (size_t)b * DDIM * TDIM + (size_t)d * TDIM + t0 + (tq << 2)) = o;
        }
    }
    if (wlen && blockIdx.x == 0 && tid < BDIMS)
        out[BDT + NQBT + tid] = (float)inlen[tid];
}

extern "C" void kernel_launch(void* const* d_in, const int* in_sizes, int n_in,
                              void* d_out, int out_size)
{
    const float* z   = (const float*)d_in[0];
    const float* iw  = (const float*)d_in[1];
    const float* ib  = (const float*)d_in[2];
    const float* ow  = (const float*)d_in[3];
    const float* ob  = (const float*)d_in[4];
    const float* cbk = (const float*)d_in[5];
    const int* inlen = (const int*)d_in[6];
    float* out = (float*)d_out;

    cudaFuncSetAttribute(rvq_kernel, cudaFuncAttributeMaxDynamicSharedMemorySize, SM_BYTES);

    int wout = (out_size >= BDT) ? 1 : 0;
    int widx = (out_size >= BDT + NQBT) ? 1 : 0;
    int wlen = (out_size >= BDT + NQBT + BDIMS) ? 1 : 0;

    prep0_kernel<<<4, 256>>>(ob);
    prep_kernel<<<256, 512>>>(ow, cbk);
    prepVc_kernel<<<NQ, 256>>>(iw);
    rvq_kernel<<<NCOLS / TILE, NTH, SM_BYTES>>>(z, iw, ib, cbk, inlen,
                                               out, wout, widx, wlen);
}